// round 7
// baseline (speedup 1.0000x reference)
#include <cuda_runtime.h>
#include <cstdint>

#define NQ      8
#define NLAYERS 4
#define DIN     1024
#define DOUT    1024
#define BMAX    8192

using ull = unsigned long long;

// ---------------- packed f32x2 helpers (Blackwell dual-FP32) ----------------
__device__ __forceinline__ ull pk(float x, float y) {
    ull r; asm("mov.b64 %0,{%1,%2};" : "=l"(r) : "f"(x), "f"(y)); return r;
}
__device__ __forceinline__ void up2(ull a, float& x, float& y) {
    asm("mov.b64 {%0,%1},%2;" : "=f"(x), "=f"(y) : "l"(a));
}
__device__ __forceinline__ ull dup2(float x) { return pk(x, x); }
__device__ __forceinline__ ull fma2(ull a, ull b, ull c) {
    ull d; asm("fma.rn.f32x2 %0,%1,%2,%3;" : "=l"(d) : "l"(a), "l"(b), "l"(c)); return d;
}
__device__ __forceinline__ ull mul2(ull a, ull b) {
    ull d; asm("mul.rn.f32x2 %0,%1,%2;" : "=l"(d) : "l"(a), "l"(b)); return d;
}
__device__ __forceinline__ ull add2(ull a, ull b) {
    ull d; asm("add.rn.f32x2 %0,%1,%2;" : "=l"(d) : "l"(a), "l"(b)); return d;
}
__device__ __forceinline__ ull swp(ull a) { float x, y; up2(a, x, y); return pk(y, x); }
__device__ __forceinline__ ull shflx(ull a, int m) {
    float x, y; up2(a, x, y);
    x = __shfl_xor_sync(0xffffffffu, x, m);
    y = __shfl_xor_sync(0xffffffffu, y, m);
    return pk(x, y);
}

// ---------------- device buffers / gate coefficients ----------------
__device__ float  g_ucoef[NLAYERS * NQ * 8];
__device__ float2 g_cs[BMAX * NQ];   // (cos(h), sin(h)) per row per wire

// ================= K1: angles = x @ Win^T + bin ; store (cos,sin) =========
// block=128 (4 warps). Warp w owns wires {2w, 2w+1}: its Win slice lives in
// 32 packed f32x2 registers for the whole block. Per row: coalesced x load,
// 32 fma2, packed butterfly, sincos. Zero Win traffic in the row loop.
#define K1_ROWS 8
__global__ __launch_bounds__(128)
void k1_angles(const float* __restrict__ x,
               const float* __restrict__ Win,
               const float* __restrict__ bin,
               const float* __restrict__ qw)
{
    const int lane = threadIdx.x & 31;
    const int warp = threadIdx.x >> 5;
    const int q0   = warp * 2;
    const int row0 = blockIdx.x * K1_ROWS;

    // Win slice for wires q0, q0+1 packed as (w_q0, w_q1) pairs
    const float4* w4 = reinterpret_cast<const float4*>(Win);
    ull wreg[32];
#pragma unroll
    for (int j = 0; j < 8; j++) {
        float4 wa = __ldg(&w4[q0 * 256 + lane + 32 * j]);
        float4 wb = __ldg(&w4[(q0 + 1) * 256 + lane + 32 * j]);
        wreg[4 * j + 0] = pk(wa.x, wb.x);
        wreg[4 * j + 1] = pk(wa.y, wb.y);
        wreg[4 * j + 2] = pk(wa.z, wb.z);
        wreg[4 * j + 3] = pk(wa.w, wb.w);
    }
    const float b0 = __ldg(&bin[q0]);
    const float b1 = __ldg(&bin[q0 + 1]);

#pragma unroll
    for (int r = 0; r < K1_ROWS; r++) {
        const int row = row0 + r;
        const float4* x4 = reinterpret_cast<const float4*>(x + (size_t)row * DIN);
        float4 xv[8];
#pragma unroll
        for (int j = 0; j < 8; j++) xv[j] = __ldg(&x4[lane + 32 * j]);

        ull a0 = dup2(0.f), a1 = dup2(0.f), a2 = dup2(0.f), a3 = dup2(0.f);
#pragma unroll
        for (int j = 0; j < 8; j++) {
            a0 = fma2(wreg[4 * j + 0], dup2(xv[j].x), a0);
            a1 = fma2(wreg[4 * j + 1], dup2(xv[j].y), a1);
            a2 = fma2(wreg[4 * j + 2], dup2(xv[j].z), a2);
            a3 = fma2(wreg[4 * j + 3], dup2(xv[j].w), a3);
        }
        ull acc = add2(add2(a0, a1), add2(a2, a3));
#pragma unroll
        for (int off = 16; off; off >>= 1)
            acc = add2(acc, shflx(acc, off));

        if (lane == 0) {
            float h0, h1;
            up2(acc, h0, h1);
            float c0, s0, c1, s1;
            __sincosf(0.5f * (h0 + b0), &s0, &c0);
            __sincosf(0.5f * (h1 + b1), &s1, &c1);
            *reinterpret_cast<float4*>(&g_cs[(size_t)row * NQ + q0]) =
                make_float4(c0, s0, c1, s1);
        }
    }

    // gate-coefficient prep (one warp of block 0)
    if (blockIdx.x == 0 && threadIdx.x < NLAYERS * NQ) {
        int t = threadIdx.x;
        int l = t >> 3, i = t & 7;
        float th = qw[l * 16 + i];        // weights[l][0][i] (RX)
        float ph = qw[l * 16 + 8 + i];    // weights[l][1][i] (RZ)
        float s2, c2, sp, cp;
        sincosf(0.5f * th, &s2, &c2);
        sincosf(0.5f * ph, &sp, &cp);
        float* u = &g_ucoef[t * 8];
        u[0] =  c2 * cp;  u[1] = -c2 * sp;   // u00
        u[2] = -s2 * sp;  u[3] = -s2 * cp;   // u01
        u[4] =  s2 * sp;  u[5] = -s2 * cp;   // u10
        u[6] =  c2 * cp;  u[7] =  c2 * sp;   // u11
    }
}

// ================= K23: circuit + output GEMM, fused ======================
// Phase A: warp w simulates row (blockIdx*8 + w); ev -> smem.
// Phase B: 256 threads x 4 cols each: out = ev @ Wout^T + bout, Wout in regs.
template<int M, int R>
__device__ __forceinline__ void apply_gate(ull* Ar, ull* Ai,
                                           float4 ua, float4 ub, int lane)
{
    constexpr int lm    = M >> 3;        // lane shuffle mask
    constexpr int loj   = (M & 7) >> 1;  // packed-register xor
    constexpr int lo0   = M & 1;         // crosses packed pair -> swp
    constexpr int Rlane = R >> 3;
    constexpr int Rj    = (R & 7) >> 1;
    constexpr int R0    = R & 1;

    const bool pl = (__popc(lane & Rlane) & 1) != 0;

    ull o_r[4], o_i[4];
#pragma unroll
    for (int j = 0; j < 4; j++) { o_r[j] = Ar[j]; o_i[j] = Ai[j]; }

#pragma unroll
    for (int j = 0; j < 4; j++) {
        ull Pr = o_r[j ^ loj], Pi = o_i[j ^ loj];
        if (lo0) { Pr = swp(Pr); Pi = swp(Pi); }
        if (lm)  { Pr = shflx(Pr, lm); Pi = shflx(Pi, lm); }
        const bool b = pl ^ (((__popc(j & Rj)) & 1) != 0);
        ull dr, di, ndi, orr, oi, noi;
        if (R0 == 0) {
            float fdr = b ? ub.z : ua.x, fdi = b ? ub.w : ua.y;
            float foR = b ? ub.x : ua.z, foI = b ? ub.y : ua.w;
            dr = dup2(fdr); di = dup2(fdi); ndi = dup2(-fdi);
            orr = dup2(foR); oi = dup2(foI); noi = dup2(-foI);
        } else {
            dr  = b ? pk(ub.z,  ua.x)  : pk(ua.x,  ub.z);
            di  = b ? pk(ub.w,  ua.y)  : pk(ua.y,  ub.w);
            ndi = b ? pk(-ub.w, -ua.y) : pk(-ua.y, -ub.w);
            orr = b ? pk(ub.x,  ua.z)  : pk(ua.z,  ub.x);
            oi  = b ? pk(ub.y,  ua.w)  : pk(ua.w,  ub.y);
            noi = b ? pk(-ub.y, -ua.w) : pk(-ua.w, -ub.y);
        }
        Ar[j] = fma2(noi, Pi, fma2(orr, Pr, fma2(ndi, o_i[j], mul2(dr, o_r[j]))));
        Ai[j] = fma2(oi,  Pr, fma2(orr, Pi, fma2(di,  o_r[j], mul2(dr, o_i[j]))));
    }
}

__global__ __launch_bounds__(256)
void k23_circuit_out(const float* __restrict__ Wout,
                     const float* __restrict__ bout,
                     float* __restrict__ out)
{
    const int lane = threadIdx.x & 31;
    const int warp = threadIdx.x >> 5;
    const int row0 = blockIdx.x * 8;
    const int row  = row0 + warp;

    __shared__ float ev_s[64];          // [r][q]

    // ---------------- Phase A: circuit for this warp's row ----------------
    float C[NQ], S[NQ];
    {
        const float4* cs4 = reinterpret_cast<const float4*>(&g_cs[(size_t)row * NQ]);
#pragma unroll
        for (int j = 0; j < 4; j++) {
            float4 v = __ldg(&cs4[j]);
            C[2 * j] = v.x; S[2 * j] = v.y; C[2 * j + 1] = v.z; S[2 * j + 1] = v.w;
        }
    }

    // initial product state (identity frame)
    float ar[8], ai[8];
    {
        float prr = 1.f, pri = 0.f;
#pragma unroll
        for (int w = 0; w < 5; w++) {
            int b = (lane >> (4 - w)) & 1;
            float qr = b ? S[w] * S[w] : C[w] * C[w];
            float qi = -S[w] * C[w];
            float nr = prr * qr - pri * qi;
            pri = prr * qi + pri * qr;
            prr = nr;
        }
#pragma unroll
        for (int r = 0; r < 8; r++) {
            float lr = prr, li = pri;
#pragma unroll
            for (int w = 5; w < 8; w++) {
                int b = (r >> (7 - w)) & 1;
                float qr = b ? S[w] * S[w] : C[w] * C[w];
                float qi = -S[w] * C[w];
                float nr = lr * qr - li * qi;
                li = lr * qi + li * qr;
                lr = nr;
            }
            ar[r] = lr; ai[r] = li;
        }
    }
    ull Ar[4], Ai[4];
#pragma unroll
    for (int j = 0; j < 4; j++) {
        Ar[j] = pk(ar[2 * j], ar[2 * j + 1]);
        Ai[j] = pk(ai[2 * j], ai[2 * j + 1]);
    }

    const float4* u4 = reinterpret_cast<const float4*>(g_ucoef);
#define G(L, I, MM, RR) { float4 ua = __ldg(&u4[((L) * 8 + (I)) * 2]); \
                          float4 ub = __ldg(&u4[((L) * 8 + (I)) * 2 + 1]); \
                          apply_gate<MM, RR>(Ar, Ai, ua, ub, lane); }
    // layer 1 (identity frame)
    G(0,0,0x80,0x80) G(0,1,0x40,0x40) G(0,2,0x20,0x20) G(0,3,0x10,0x10)
    G(0,4,0x08,0x08) G(0,5,0x04,0x04) G(0,6,0x02,0x02) G(0,7,0x01,0x01)
    // layer 2 (after CNOT chain 1)
    G(1,0,0xC0,0x80) G(1,1,0x60,0xC0) G(1,2,0x30,0xE0) G(1,3,0x18,0xF0)
    G(1,4,0x0C,0xF8) G(1,5,0x06,0xFC) G(1,6,0x03,0xFE) G(1,7,0x01,0xFF)
    // layer 3
    G(2,0,0xA0,0x80) G(2,1,0x50,0x40) G(2,2,0x28,0xA0) G(2,3,0x14,0x50)
    G(2,4,0x0A,0xA8) G(2,5,0x05,0x54) G(2,6,0x02,0xAA) G(2,7,0x01,0x55)
    // layer 4
    G(3,0,0xF0,0x80) G(3,1,0x78,0xC0) G(3,2,0x3C,0x60) G(3,3,0x1E,0x30)
    G(3,4,0x0F,0x98) G(3,5,0x07,0xCC) G(3,6,0x03,0x66) G(3,7,0x01,0x33)
#undef G

    // probabilities
    ull P[4];
#pragma unroll
    for (int j = 0; j < 4; j++) P[j] = fma2(Ai[j], Ai[j], mul2(Ar[j], Ar[j]));
    float p[8];
#pragma unroll
    for (int j = 0; j < 4; j++) up2(P[j], p[2 * j], p[2 * j + 1]);

    float ptot = ((p[0] + p[1]) + (p[2] + p[3])) + ((p[4] + p[5]) + (p[6] + p[7]));

    // final sign rows Rf = [0x80,0x40,0x20,0x10,0x88,0x44,0x22,0x11]
    float s5 = ((p[0] + p[1]) + (p[2] + p[3])) - ((p[4] + p[5]) + (p[6] + p[7]));
    float s6 = ((p[0] + p[1]) - (p[2] + p[3])) + ((p[4] + p[5]) - (p[6] + p[7]));
    float s7 = ((p[0] - p[1]) + (p[2] - p[3])) + ((p[4] - p[5]) + (p[6] - p[7]));

    float ev[NQ];
    ev[0] = (__popc(lane & 0x10) & 1) ? -ptot : ptot;
    ev[1] = (__popc(lane & 0x08) & 1) ? -ptot : ptot;
    ev[2] = (__popc(lane & 0x04) & 1) ? -ptot : ptot;
    ev[3] = (__popc(lane & 0x02) & 1) ? -ptot : ptot;
    ev[4] = (__popc(lane & 0x11) & 1) ? -ptot : ptot;
    ev[5] = (__popc(lane & 0x08) & 1) ? -s5 : s5;
    ev[6] = (__popc(lane & 0x04) & 1) ? -s6 : s6;
    ev[7] = (__popc(lane & 0x02) & 1) ? -s7 : s7;

#pragma unroll
    for (int off = 16; off; off >>= 1)
#pragma unroll
        for (int i = 0; i < NQ; i++)
            ev[i] += __shfl_xor_sync(0xffffffffu, ev[i], off);

    // static predicated gather, write to smem
    float myev = ev[0];
#pragma unroll
    for (int i = 1; i < NQ; i++)
        if (lane == i) myev = ev[i];
    if (lane < NQ)
        ev_s[warp * NQ + lane] = myev;

    __syncthreads();

    // ---------------- Phase B: out[row0..row0+7] = ev @ Wout^T + bout -----
    const int c0 = threadIdx.x * 4;
    const float4* wo4 = reinterpret_cast<const float4*>(Wout);  // [DOUT][2]
    float4 wa[4], wb[4];
#pragma unroll
    for (int k = 0; k < 4; k++) {
        wa[k] = __ldg(&wo4[(c0 + k) * 2 + 0]);
        wb[k] = __ldg(&wo4[(c0 + k) * 2 + 1]);
    }
    float4 bo = __ldg(&reinterpret_cast<const float4*>(bout)[threadIdx.x]);

#pragma unroll
    for (int r = 0; r < 8; r++) {
        float4 ea = *reinterpret_cast<const float4*>(&ev_s[r * NQ]);
        float4 eb = *reinterpret_cast<const float4*>(&ev_s[r * NQ + 4]);
        float4 o;
        o.x = bo.x + ea.x * wa[0].x + ea.y * wa[0].y + ea.z * wa[0].z + ea.w * wa[0].w
                   + eb.x * wb[0].x + eb.y * wb[0].y + eb.z * wb[0].z + eb.w * wb[0].w;
        o.y = bo.y + ea.x * wa[1].x + ea.y * wa[1].y + ea.z * wa[1].z + ea.w * wa[1].w
                   + eb.x * wb[1].x + eb.y * wb[1].y + eb.z * wb[1].z + eb.w * wb[1].w;
        o.z = bo.z + ea.x * wa[2].x + ea.y * wa[2].y + ea.z * wa[2].z + ea.w * wa[2].w
                   + eb.x * wb[2].x + eb.y * wb[2].y + eb.z * wb[2].z + eb.w * wb[2].w;
        o.w = bo.w + ea.x * wa[3].x + ea.y * wa[3].y + ea.z * wa[3].z + ea.w * wa[3].w
                   + eb.x * wb[3].x + eb.y * wb[3].y + eb.z * wb[3].z + eb.w * wb[3].w;
        reinterpret_cast<float4*>(out + (size_t)(row0 + r) * DOUT)[threadIdx.x] = o;
    }
}

extern "C" void kernel_launch(void* const* d_in, const int* in_sizes, int n_in,
                              void* d_out, int out_size) {
    const float* x    = (const float*)d_in[0];
    const float* Win  = (const float*)d_in[1];
    const float* bin  = (const float*)d_in[2];
    const float* qw   = (const float*)d_in[3];
    const float* Wout = (const float*)d_in[4];
    const float* bout = (const float*)d_in[5];
    float* out = (float*)d_out;

    int B = in_sizes[0] / DIN;            // 8192
    k1_angles<<<B / K1_ROWS, 128>>>(x, Win, bin, qw);
    k23_circuit_out<<<B / 8, 256>>>(Wout, bout, out);
}

// round 9
// speedup vs baseline: 1.1268x; 1.1268x over previous
#include <cuda_runtime.h>
#include <cstdint>

#define NQ      8
#define NLAYERS 4
#define DIN     1024
#define DOUT    1024
#define BMAX    8192

using ull = unsigned long long;

// ---------------- packed f32x2 helpers (Blackwell dual-FP32) ----------------
__device__ __forceinline__ ull pk(float x, float y) {
    ull r; asm("mov.b64 %0,{%1,%2};" : "=l"(r) : "f"(x), "f"(y)); return r;
}
__device__ __forceinline__ void up2(ull a, float& x, float& y) {
    asm("mov.b64 {%0,%1},%2;" : "=f"(x), "=f"(y) : "l"(a));
}
__device__ __forceinline__ ull dup2(float x) { return pk(x, x); }
__device__ __forceinline__ ull fma2(ull a, ull b, ull c) {
    ull d; asm("fma.rn.f32x2 %0,%1,%2,%3;" : "=l"(d) : "l"(a), "l"(b), "l"(c)); return d;
}
__device__ __forceinline__ ull mul2(ull a, ull b) {
    ull d; asm("mul.rn.f32x2 %0,%1,%2;" : "=l"(d) : "l"(a), "l"(b)); return d;
}
__device__ __forceinline__ ull add2(ull a, ull b) {
    ull d; asm("add.rn.f32x2 %0,%1,%2;" : "=l"(d) : "l"(a), "l"(b)); return d;
}
__device__ __forceinline__ ull neg2(ull a) { return a ^ 0x8000000080000000ULL; }
__device__ __forceinline__ ull sub2(ull a, ull b) { return add2(a, neg2(b)); }
__device__ __forceinline__ ull swp(ull a) { float x, y; up2(a, x, y); return pk(y, x); }
__device__ __forceinline__ ull shflx(ull a, int m) {
    float x, y; up2(a, x, y);
    x = __shfl_xor_sync(0xffffffffu, x, m);
    y = __shfl_xor_sync(0xffffffffu, y, m);
    return pk(x, y);
}

// ---------------- device buffers / gate coefficients ----------------
__device__ float  g_ucoef[NLAYERS * NQ * 8];
__device__ float2 g_cs[BMAX * NQ];   // (cos(h), sin(h)) per row per wire

// ================= K1: angles = x @ Win^T + bin ; store (cos,sin) =========
// block=128 (4 warps), 2 rows per warp (each warp owns DIFFERENT rows -> x is
// read exactly once chip-wide). Win staged in 32KB smem once per block.
__global__ __launch_bounds__(128)
void k1_angles(const float* __restrict__ x,
               const float* __restrict__ Win,
               const float* __restrict__ bin,
               const float* __restrict__ qw)
{
    __shared__ float sW[NQ * DIN];     // 32 KB

    const int tid  = threadIdx.x;
    const int lane = tid & 31;
    const int warp = tid >> 5;
    const int row0 = blockIdx.x * 8 + warp * 2;

    // front-batch the DRAM x loads for both rows (16 LDG.128 in flight)
    const float4* xr0 = reinterpret_cast<const float4*>(x + (size_t)row0 * DIN);
    const float4* xr1 = reinterpret_cast<const float4*>(x + (size_t)(row0 + 1) * DIN);
    float4 xa[8], xb[8];
#pragma unroll
    for (int j = 0; j < 8; j++) xa[j] = __ldcs(&xr0[lane + 32 * j]);
#pragma unroll
    for (int j = 0; j < 8; j++) xb[j] = __ldcs(&xr1[lane + 32 * j]);

    // stage Win into smem (L2-hot after first block)
    {
        const float4* w4g = reinterpret_cast<const float4*>(Win);
        float4* sW4 = reinterpret_cast<float4*>(sW);
#pragma unroll
        for (int i = 0; i < 16; i++)
            sW4[tid + 128 * i] = __ldg(&w4g[tid + 128 * i]);
    }
    __syncthreads();

    float acc[2][8];
#pragma unroll
    for (int r = 0; r < 2; r++)
#pragma unroll
        for (int q = 0; q < NQ; q++) acc[r][q] = 0.f;

    const float4* sW4 = reinterpret_cast<const float4*>(sW);
#pragma unroll
    for (int j = 0; j < 8; j++) {
#pragma unroll
        for (int q = 0; q < NQ; q++) {
            float4 wv = sW4[q * 256 + lane + 32 * j];
            acc[0][q] += xa[j].x * wv.x + xa[j].y * wv.y
                       + xa[j].z * wv.z + xa[j].w * wv.w;
            acc[1][q] += xb[j].x * wv.x + xb[j].y * wv.y
                       + xb[j].z * wv.z + xb[j].w * wv.w;
        }
    }

    // pack (row, q-pair) and butterfly-reduce over 32 lanes
    ull A8[8];
#pragma unroll
    for (int r = 0; r < 2; r++)
#pragma unroll
        for (int qh = 0; qh < 4; qh++)
            A8[r * 4 + qh] = pk(acc[r][2 * qh], acc[r][2 * qh + 1]);
#pragma unroll
    for (int off = 16; off; off >>= 1)
#pragma unroll
        for (int k = 0; k < 8; k++)
            A8[k] = add2(A8[k], shflx(A8[k], off));

    // lane o = r*8+q takes its h (static predicated unpack)
    float h = 0.f;
#pragma unroll
    for (int o = 0; o < 16; o++) {
        if (lane == o) {
            float hx, hy;
            up2(A8[(o >> 3) * 4 + ((o & 7) >> 1)], hx, hy);
            h = (o & 1) ? hy : hx;
        }
    }
    if (lane < 16) {
        const int rr = lane >> 3;
        const int qq = lane & 7;
        float c, s;
        __sincosf(0.5f * (h + __ldg(&bin[qq])), &s, &c);
        g_cs[(size_t)(row0 + rr) * NQ + qq] = make_float2(c, s);
    }

    // gate-coefficient prep (one warp of block 0)
    if (blockIdx.x == 0 && tid < NLAYERS * NQ) {
        int t = tid;
        int l = t >> 3, i = t & 7;
        float th = qw[l * 16 + i];        // weights[l][0][i] (RX)
        float ph = qw[l * 16 + 8 + i];    // weights[l][1][i] (RZ)
        float s2, c2, sp, cp;
        sincosf(0.5f * th, &s2, &c2);
        sincosf(0.5f * ph, &sp, &cp);
        float* u = &g_ucoef[t * 8];
        u[0] =  c2 * cp;  u[1] = -c2 * sp;   // u00
        u[2] = -s2 * sp;  u[3] = -s2 * cp;   // u01
        u[4] =  s2 * sp;  u[5] = -s2 * cp;   // u10
        u[6] =  c2 * cp;  u[7] =  c2 * sp;   // u11
    }
}

// ================= K23: circuit (8 lanes/row, 32 amps/lane) + output GEMM ==
// Warp = 4 groups of 8 lanes; group g simulates one row. Physical amp
// p[7:0]: bits7..5 = group-lane bits l[2:0], bits4..0 = local r. Packed f32x2
// pairs over bit0: reg j = r>>1 (16 ull per component).
// Gate on frame mask M, parity row R: lane part = M>>5, local reg xor =
// (M&31)>>1, packed-cross = M&1 (same split for R).

template<int M, int R>
__device__ __forceinline__ void apply_gate16(ull* Ar, ull* Ai,
                                             float4 ua, float4 ub, int l)
{
    constexpr int lm    = M >> 5;
    constexpr int loj   = (M & 31) >> 1;
    constexpr int lo0   = M & 1;
    constexpr int Rlane = R >> 5;
    constexpr int Rj    = (R & 31) >> 1;
    constexpr int R0    = R & 1;

    const bool pl = (__popc(l & Rlane) & 1) != 0;

    // coefficient sets: parity-0 set (u00 diag / u01 off) and parity-1 set
    // (u11 / u10); for R0==1 the two packed slots have opposite parity.
    ull c0_dr, c0_di, c0_or, c0_oi;
    ull c1_dr, c1_di, c1_or, c1_oi;
    if (R0 == 0) {
        c0_dr = dup2(ua.x); c0_di = dup2(ua.y); c0_or = dup2(ua.z); c0_oi = dup2(ua.w);
        c1_dr = dup2(ub.z); c1_di = dup2(ub.w); c1_or = dup2(ub.x); c1_oi = dup2(ub.y);
    } else {
        c0_dr = pk(ua.x, ub.z); c0_di = pk(ua.y, ub.w);
        c0_or = pk(ua.z, ub.x); c0_oi = pk(ua.w, ub.y);
        c1_dr = pk(ub.z, ua.x); c1_di = pk(ub.w, ua.y);
        c1_or = pk(ub.x, ua.z); c1_oi = pk(ub.y, ua.w);
    }
    const ull e_dr = pl ? c1_dr : c0_dr, e_di = pl ? c1_di : c0_di;
    const ull e_or = pl ? c1_or : c0_or, e_oi = pl ? c1_oi : c0_oi;
    const ull o_dr = pl ? c0_dr : c1_dr, o_di = pl ? c0_di : c1_di;
    const ull o_or = pl ? c0_or : c1_or, o_oi = pl ? c0_oi : c1_oi;
    const ull e_ndi = neg2(e_di), e_noi = neg2(e_oi);
    const ull o_ndi = neg2(o_di), o_noi = neg2(o_oi);

#define GUPD(jj, cjj, PR, PI)                                                  \
    {   ull mr = Ar[jj], mi = Ai[jj];                                          \
        if (cjj) {                                                             \
            Ar[jj] = fma2(o_noi, PI, fma2(o_or, PR, fma2(o_ndi, mi, mul2(o_dr, mr)))); \
            Ai[jj] = fma2(o_oi,  PR, fma2(o_or, PI, fma2(o_di,  mr, mul2(o_dr, mi)))); \
        } else {                                                               \
            Ar[jj] = fma2(e_noi, PI, fma2(e_or, PR, fma2(e_ndi, mi, mul2(e_dr, mr)))); \
            Ai[jj] = fma2(e_oi,  PR, fma2(e_or, PI, fma2(e_di,  mr, mul2(e_dr, mi)))); \
        } }

    if (loj == 0) {
#pragma unroll
        for (int j = 0; j < 16; j++) {
            ull Pr = Ar[j], Pi_ = Ai[j];
            if (lo0) { Pr = swp(Pr); Pi_ = swp(Pi_); }
            if (lm)  { Pr = shflx(Pr, lm); Pi_ = shflx(Pi_, lm); }
            const int cj = __popc(j & Rj) & 1;
            GUPD(j, cj, Pr, Pi_)
        }
    } else {
#pragma unroll
        for (int j = 0; j < 16; j++) {
            const int j2 = j ^ loj;
            if (j < j2) {
                ull Par = Ar[j2], Pai = Ai[j2];   // partner source for output j
                ull Pbr = Ar[j],  Pbi = Ai[j];    // partner source for output j2
                if (lo0) { Par = swp(Par); Pai = swp(Pai); Pbr = swp(Pbr); Pbi = swp(Pbi); }
                if (lm)  { Par = shflx(Par, lm); Pai = shflx(Pai, lm);
                           Pbr = shflx(Pbr, lm); Pbi = shflx(Pbi, lm); }
                const int cj  = __popc(j  & Rj) & 1;
                const int cj2 = __popc(j2 & Rj) & 1;
                GUPD(j,  cj,  Par, Pai)
                GUPD(j2, cj2, Pbr, Pbi)
            }
        }
    }
#undef GUPD
}

__global__ __launch_bounds__(128)
void k23_circuit_out(const float* __restrict__ Wout,
                     const float* __restrict__ bout,
                     float* __restrict__ out)
{
    const int tid  = threadIdx.x;
    const int lane = tid & 31;
    const int warp = tid >> 5;
    const int l    = lane & 7;         // lane within 8-lane group
    const int g    = lane >> 3;        // group = row within warp
    const int row0 = blockIdx.x * 16;
    const int rib  = warp * 4 + g;     // row in block (0..15)
    const int row  = row0 + rib;

    __shared__ float ev_s[16 * NQ];

    // per-row (cos,sin)
    float C[NQ], S[NQ];
    {
        const float4* cs4 = reinterpret_cast<const float4*>(&g_cs[(size_t)row * NQ]);
#pragma unroll
        for (int j = 0; j < 4; j++) {
            float4 v = __ldg(&cs4[j]);
            C[2 * j] = v.x; S[2 * j] = v.y; C[2 * j + 1] = v.z; S[2 * j + 1] = v.w;
        }
    }

    // initial product state: lane wires 0..2 (l bits 2..0), local wires 3..7
    float ar[32], ai[32];
    {
        float prr = 1.f, pri = 0.f;
#pragma unroll
        for (int w = 0; w < 3; w++) {
            int b = (l >> (2 - w)) & 1;
            float qr = b ? S[w] * S[w] : C[w] * C[w];
            float qi = -S[w] * C[w];
            float nr = prr * qr - pri * qi;
            pri = prr * qi + pri * qr;
            prr = nr;
        }
        ar[0] = prr; ai[0] = pri;
        int cnt = 1;
#pragma unroll
        for (int w = 7; w >= 3; w--) {      // wire w -> local bit (7-w)
            float q0r = C[w] * C[w], q1r = S[w] * S[w], qi = -S[w] * C[w];
#pragma unroll
            for (int j = 0; j < 16; j++) {
                if (j < cnt) {
                    float br = ar[j], bi = ai[j];
                    ar[j + cnt] = br * q1r - bi * qi;
                    ai[j + cnt] = br * qi + bi * q1r;
                    ar[j] = br * q0r - bi * qi;
                    ai[j] = br * qi + bi * q0r;
                }
            }
            cnt <<= 1;
        }
    }
    ull Ar[16], Ai[16];
#pragma unroll
    for (int j = 0; j < 16; j++) {
        Ar[j] = pk(ar[2 * j], ar[2 * j + 1]);
        Ai[j] = pk(ai[2 * j], ai[2 * j + 1]);
    }

    const float4* u4 = reinterpret_cast<const float4*>(g_ucoef);
#define G(L, I, MM, RR) { float4 ua = __ldg(&u4[((L) * 8 + (I)) * 2]); \
                          float4 ub = __ldg(&u4[((L) * 8 + (I)) * 2 + 1]); \
                          apply_gate16<MM, RR>(Ar, Ai, ua, ub, l); }
    // layer 1 (identity frame)
    G(0,0,0x80,0x80) G(0,1,0x40,0x40) G(0,2,0x20,0x20) G(0,3,0x10,0x10)
    G(0,4,0x08,0x08) G(0,5,0x04,0x04) G(0,6,0x02,0x02) G(0,7,0x01,0x01)
    // layer 2
    G(1,0,0xC0,0x80) G(1,1,0x60,0xC0) G(1,2,0x30,0xE0) G(1,3,0x18,0xF0)
    G(1,4,0x0C,0xF8) G(1,5,0x06,0xFC) G(1,6,0x03,0xFE) G(1,7,0x01,0xFF)
    // layer 3
    G(2,0,0xA0,0x80) G(2,1,0x50,0x40) G(2,2,0x28,0xA0) G(2,3,0x14,0x50)
    G(2,4,0x0A,0xA8) G(2,5,0x05,0x54) G(2,6,0x02,0xAA) G(2,7,0x01,0x55)
    // layer 4
    G(3,0,0xF0,0x80) G(3,1,0x78,0xC0) G(3,2,0x3C,0x60) G(3,3,0x1E,0x30)
    G(3,4,0x0F,0x98) G(3,5,0x07,0xCC) G(3,6,0x03,0x66) G(3,7,0x01,0x33)
#undef G

    // probabilities (packed) and signed local sums via shared tree
    ull P[16];
#pragma unroll
    for (int j = 0; j < 16; j++) P[j] = fma2(Ai[j], Ai[j], mul2(Ar[j], Ar[j]));

    ull s1[8], d1[8];
#pragma unroll
    for (int k = 0; k < 8; k++) { s1[k] = add2(P[2 * k], P[2 * k + 1]);
                                  d1[k] = sub2(P[2 * k], P[2 * k + 1]); }
    ull s2[4], d2[4];
#pragma unroll
    for (int k = 0; k < 4; k++) { s2[k] = add2(s1[2 * k], s1[2 * k + 1]);
                                  d2[k] = sub2(s1[2 * k], s1[2 * k + 1]); }
    ull s3a = add2(s2[0], s2[1]), s3b = add2(s2[2], s2[3]);
    ull d3a = sub2(s2[0], s2[1]), d3b = sub2(s2[2], s2[3]);
    ull T   = add2(s3a, s3b);                     // all +
    ull D16 = sub2(s3a, s3b);                     // sign: r bit4
    ull D8  = add2(d3a, d3b);                     // sign: r bit3
    ull D4  = add2(add2(d2[0], d2[1]), add2(d2[2], d2[3]));   // r bit2
    ull D2  = add2(add2(add2(d1[0], d1[1]), add2(d1[2], d1[3])),
                   add2(add2(d1[4], d1[5]), add2(d1[6], d1[7])));  // r bit1

    float tx, ty;  up2(T,  tx, ty);  float ptot = tx + ty;
    float ax, ay;  up2(D16, ax, ay); float L10 = ax + ay, L11 = ax - ay;
    float bx, by;  up2(D8,  bx, by); float L08 = bx + by;
    float cx, cy;  up2(D4,  cx, cy); float L04 = cx + cy;
    float dx, dy;  up2(D2,  dx, dy); float L02 = dx + dy;

    // ev sign rows Rf = [0x80,0x40,0x20,0x10,0x88,0x44,0x22,0x11]
    float e0 = (l & 4) ? -ptot : ptot;
    float e1 = (l & 2) ? -ptot : ptot;
    float e2 = (l & 1) ? -ptot : ptot;
    float e3 = L10;
    float e4 = (l & 4) ? -L08 : L08;
    float e5 = (l & 2) ? -L04 : L04;
    float e6 = (l & 1) ? -L02 : L02;
    float e7 = L11;

    ull E[4] = { pk(e0, e1), pk(e2, e3), pk(e4, e5), pk(e6, e7) };
#pragma unroll
    for (int off = 4; off; off >>= 1)
#pragma unroll
        for (int k = 0; k < 4; k++)
            E[k] = add2(E[k], shflx(E[k], off));

    // lane l writes ev[l] for its row (static predicated unpack)
    float myev = 0.f;
#pragma unroll
    for (int o = 0; o < 8; o++) {
        if (l == o) {
            float vx, vy; up2(E[o >> 1], vx, vy);
            myev = (o & 1) ? vy : vx;
        }
    }
    ev_s[rib * NQ + l] = myev;
    __syncthreads();

    // ---------------- Phase B: out = ev @ Wout^T + bout -------------------
    // thread owns float4 col groups {tid, 128+tid}; packed over col pairs.
    const float4* wo4 = reinterpret_cast<const float4*>(Wout);  // [DOUT][2]
    ull w[4][8];
    ull bo[4];
#pragma unroll
    for (int pp = 0; pp < 4; pp++) {
        int c0p = ((pp < 2) ? tid * 4 : 512 + tid * 4) + (pp & 1) * 2;
        float4 wa0 = __ldg(&wo4[c0p * 2 + 0]);
        float4 wa1 = __ldg(&wo4[c0p * 2 + 1]);
        float4 wb0 = __ldg(&wo4[(c0p + 1) * 2 + 0]);
        float4 wb1 = __ldg(&wo4[(c0p + 1) * 2 + 1]);
        w[pp][0] = pk(wa0.x, wb0.x); w[pp][1] = pk(wa0.y, wb0.y);
        w[pp][2] = pk(wa0.z, wb0.z); w[pp][3] = pk(wa0.w, wb0.w);
        w[pp][4] = pk(wa1.x, wb1.x); w[pp][5] = pk(wa1.y, wb1.y);
        w[pp][6] = pk(wa1.z, wb1.z); w[pp][7] = pk(wa1.w, wb1.w);
        bo[pp] = pk(__ldg(&bout[c0p]), __ldg(&bout[c0p + 1]));
    }

    float4* out4 = reinterpret_cast<float4*>(out);
#pragma unroll
    for (int r = 0; r < 16; r++) {
        ull acc0 = bo[0], acc1 = bo[1], acc2 = bo[2], acc3 = bo[3];
#pragma unroll
        for (int q = 0; q < NQ; q++) {
            ull eq = dup2(ev_s[r * NQ + q]);
            acc0 = fma2(w[0][q], eq, acc0);
            acc1 = fma2(w[1][q], eq, acc1);
            acc2 = fma2(w[2][q], eq, acc2);
            acc3 = fma2(w[3][q], eq, acc3);
        }
        float4 oA, oB;
        up2(acc0, oA.x, oA.y); up2(acc1, oA.z, oA.w);
        up2(acc2, oB.x, oB.y); up2(acc3, oB.z, oB.w);
        size_t base = (size_t)(row0 + r) * (DOUT / 4);
        out4[base + tid]       = oA;
        out4[base + 128 + tid] = oB;
    }
}

extern "C" void kernel_launch(void* const* d_in, const int* in_sizes, int n_in,
                              void* d_out, int out_size) {
    const float* x    = (const float*)d_in[0];
    const float* Win  = (const float*)d_in[1];
    const float* bin  = (const float*)d_in[2];
    const float* qw   = (const float*)d_in[3];
    const float* Wout = (const float*)d_in[4];
    const float* bout = (const float*)d_in[5];
    float* out = (float*)d_out;

    int B = in_sizes[0] / DIN;            // 8192
    k1_angles<<<B / 8, 128>>>(x, Win, bin, qw);
    k23_circuit_out<<<B / 16, 128>>>(Wout, bout, out);
}

// round 10
// speedup vs baseline: 1.1871x; 1.0536x over previous
#include <cuda_runtime.h>
#include <cstdint>

#define NQ      8
#define NLAYERS 4
#define DIN     1024
#define DOUT    1024
#define BMAX    8192

using ull = unsigned long long;
#define SGN2 0x8000000080000000ULL

// ---------------- packed f32x2 helpers (Blackwell dual-FP32) ----------------
__device__ __forceinline__ ull pk(float x, float y) {
    ull r; asm("mov.b64 %0,{%1,%2};" : "=l"(r) : "f"(x), "f"(y)); return r;
}
__device__ __forceinline__ void up2(ull a, float& x, float& y) {
    asm("mov.b64 {%0,%1},%2;" : "=f"(x), "=f"(y) : "l"(a));
}
__device__ __forceinline__ ull dup2(float x) { return pk(x, x); }
__device__ __forceinline__ ull fma2(ull a, ull b, ull c) {
    ull d; asm("fma.rn.f32x2 %0,%1,%2,%3;" : "=l"(d) : "l"(a), "l"(b), "l"(c)); return d;
}
__device__ __forceinline__ ull mul2(ull a, ull b) {
    ull d; asm("mul.rn.f32x2 %0,%1,%2;" : "=l"(d) : "l"(a), "l"(b)); return d;
}
__device__ __forceinline__ ull add2(ull a, ull b) {
    ull d; asm("add.rn.f32x2 %0,%1,%2;" : "=l"(d) : "l"(a), "l"(b)); return d;
}
__device__ __forceinline__ ull sub2(ull a, ull b) { return add2(a, b ^ SGN2); }
__device__ __forceinline__ ull swp(ull a) { float x, y; up2(a, x, y); return pk(y, x); }
__device__ __forceinline__ ull shflx(ull a, int m) {
    float x, y; up2(a, x, y);
    x = __shfl_xor_sync(0xffffffffu, x, m);
    y = __shfl_xor_sync(0xffffffffu, y, m);
    return pk(x, y);
}

// ---------------- device buffers / gate coefficients ----------------
// Per gate only u00,u01 needed (u11=conj(u00), u10=-conj(u01)).
__device__ float4 g_ucoef[NLAYERS * NQ];    // {u00r,u00i,u01r,u01i}
__device__ float2 g_cs[BMAX * NQ];          // (cos,sin) per row per wire

// ================= K1: angles = x @ Win^T + bin ; store (cos,sin) =========
__global__ __launch_bounds__(128)
void k1_angles(const float* __restrict__ x,
               const float* __restrict__ Win,
               const float* __restrict__ bin,
               const float* __restrict__ qw)
{
    __shared__ float sW[NQ * DIN];     // 32 KB

    const int tid  = threadIdx.x;
    const int lane = tid & 31;
    const int warp = tid >> 5;
    const int row0 = blockIdx.x * 8 + warp * 2;

    const float4* xr0 = reinterpret_cast<const float4*>(x + (size_t)row0 * DIN);
    const float4* xr1 = reinterpret_cast<const float4*>(x + (size_t)(row0 + 1) * DIN);
    float4 xa[8], xb[8];
#pragma unroll
    for (int j = 0; j < 8; j++) xa[j] = __ldcs(&xr0[lane + 32 * j]);
#pragma unroll
    for (int j = 0; j < 8; j++) xb[j] = __ldcs(&xr1[lane + 32 * j]);

    {
        const float4* w4g = reinterpret_cast<const float4*>(Win);
        float4* sW4 = reinterpret_cast<float4*>(sW);
#pragma unroll
        for (int i = 0; i < 16; i++)
            sW4[tid + 128 * i] = __ldg(&w4g[tid + 128 * i]);
    }
    __syncthreads();

    float acc[2][8];
#pragma unroll
    for (int r = 0; r < 2; r++)
#pragma unroll
        for (int q = 0; q < NQ; q++) acc[r][q] = 0.f;

    const float4* sW4 = reinterpret_cast<const float4*>(sW);
#pragma unroll
    for (int j = 0; j < 8; j++) {
#pragma unroll
        for (int q = 0; q < NQ; q++) {
            float4 wv = sW4[q * 256 + lane + 32 * j];
            acc[0][q] += xa[j].x * wv.x + xa[j].y * wv.y
                       + xa[j].z * wv.z + xa[j].w * wv.w;
            acc[1][q] += xb[j].x * wv.x + xb[j].y * wv.y
                       + xb[j].z * wv.z + xb[j].w * wv.w;
        }
    }

    ull A8[8];
#pragma unroll
    for (int r = 0; r < 2; r++)
#pragma unroll
        for (int qh = 0; qh < 4; qh++)
            A8[r * 4 + qh] = pk(acc[r][2 * qh], acc[r][2 * qh + 1]);
#pragma unroll
    for (int off = 16; off; off >>= 1)
#pragma unroll
        for (int k = 0; k < 8; k++)
            A8[k] = add2(A8[k], shflx(A8[k], off));

    float h = 0.f;
#pragma unroll
    for (int o = 0; o < 16; o++) {
        if (lane == o) {
            float hx, hy;
            up2(A8[(o >> 3) * 4 + ((o & 7) >> 1)], hx, hy);
            h = (o & 1) ? hy : hx;
        }
    }
    if (lane < 16) {
        const int rr = lane >> 3;
        const int qq = lane & 7;
        float c, s;
        __sincosf(0.5f * (h + __ldg(&bin[qq])), &s, &c);
        g_cs[(size_t)(row0 + rr) * NQ + qq] = make_float2(c, s);
    }

    if (blockIdx.x == 0 && tid < NLAYERS * NQ) {
        int t = tid;
        int l = t >> 3, i = t & 7;
        float th = qw[l * 16 + i];        // weights[l][0][i] (RX)
        float ph = qw[l * 16 + 8 + i];    // weights[l][1][i] (RZ)
        float s2, c2, sp, cp;
        sincosf(0.5f * th, &s2, &c2);
        sincosf(0.5f * ph, &sp, &cp);
        g_ucoef[t] = make_float4(c2 * cp, -c2 * sp, -s2 * sp, -s2 * cp);
    }
}

// ================= K23: circuit (16 lanes/row, 16 amps/lane) + output GEMM ==
// Warp = 2 groups of 16 lanes; group g simulates one row. Physical amp
// p[7:0]: bits 7..4 = group-lane l[3:0], bits 3..0 = local r. Packed pairs
// over bit0: reg j = r>>1 (8 ull per component).
// Gate with mask M, parity row R: new[p] = d(b)*old[p] + o(b)*old[p^M],
// b = popc(p&R). Conjugate structure: d(b) = (dr, ±di), o(b) = (±or, oi).

template<int M, int R>
__device__ __forceinline__ void apply_gate8(ull* Ar, ull* Ai, float4 u, int l)
{
    constexpr int lm    = M >> 4;
    constexpr int loj   = (M & 15) >> 1;
    constexpr int lo0   = M & 1;
    constexpr int Rlane = R >> 4;
    constexpr int Rj    = (R & 15) >> 1;
    constexpr int R0    = R & 1;

    const bool pl = (__popc(l & Rlane) & 1) != 0;

    const ull drP  = dup2(u.x);
    const ull oiP  = dup2(u.w);
    const ull noiP = oiP ^ SGN2;
    ull diB = (R0 == 0) ? dup2(u.y) : pk(u.y, -u.y);
    ull orB = (R0 == 0) ? dup2(u.z) : pk(u.z, -u.z);
    if (pl) { diB ^= SGN2; orB ^= SGN2; }
    const ull diN = diB ^ SGN2, orN = orB ^ SGN2;

    // nr = dr*mr - dij*mi + orj*Pr - oi*Pi ; ni = dr*mi + dij*mr + orj*Pi + oi*Pr
#define GUPD(jj, PR, PI)                                                        \
    {   const bool sj = (__popc((jj) & Rj) & 1) != 0;                           \
        const ull dij = sj ? diN : diB, ndij = sj ? diB : diN;                  \
        const ull orj = sj ? orN : orB;                                         \
        ull mr = Ar[jj], mi = Ai[jj];                                           \
        Ar[jj] = fma2(orj, PR, fma2(noiP, PI, fma2(ndij, mi, mul2(drP, mr))));  \
        Ai[jj] = fma2(oiP, PR, fma2(orj,  PI, fma2(dij,  mr, mul2(drP, mi)))); }

    if (loj == 0) {
#pragma unroll
        for (int j = 0; j < 8; j++) {
            ull Pr = Ar[j], Pi_ = Ai[j];
            if (lo0) { Pr = swp(Pr); Pi_ = swp(Pi_); }
            if (lm)  { Pr = shflx(Pr, lm); Pi_ = shflx(Pi_, lm); }
            GUPD(j, Pr, Pi_)
        }
    } else {
#pragma unroll
        for (int j = 0; j < 8; j++) {
            const int j2 = j ^ loj;
            if (j < j2) {
                ull Par = Ar[j2], Pai = Ai[j2];   // partner for output j
                ull Pbr = Ar[j],  Pbi = Ai[j];    // partner for output j2
                if (lo0) { Par = swp(Par); Pai = swp(Pai); Pbr = swp(Pbr); Pbi = swp(Pbi); }
                if (lm)  { Par = shflx(Par, lm); Pai = shflx(Pai, lm);
                           Pbr = shflx(Pbr, lm); Pbi = shflx(Pbi, lm); }
                GUPD(j,  Par, Pai)
                GUPD(j2, Pbr, Pbi)
            }
        }
    }
#undef GUPD
}

__global__ __launch_bounds__(128)
void k23_circuit_out(const float* __restrict__ Wout,
                     const float* __restrict__ bout,
                     float* __restrict__ out)
{
    const int tid  = threadIdx.x;
    const int lane = tid & 31;
    const int warp = tid >> 5;
    const int l    = lane & 15;        // lane within 16-lane group
    const int g    = lane >> 4;        // group = row within warp
    const int row0 = blockIdx.x * 8;
    const int rib  = warp * 2 + g;     // row in block (0..7)
    const int row  = row0 + rib;

    __shared__ float ev_s[8 * NQ];

    float C[NQ], S[NQ];
    {
        const float4* cs4 = reinterpret_cast<const float4*>(&g_cs[(size_t)row * NQ]);
#pragma unroll
        for (int j = 0; j < 4; j++) {
            float4 v = __ldg(&cs4[j]);
            C[2 * j] = v.x; S[2 * j] = v.y; C[2 * j + 1] = v.z; S[2 * j + 1] = v.w;
        }
    }

    // initial product state: lane wires 0..3 (l bits 3..0), wires 4..6 on
    // reg bits j[2..0], wire 7 on packed half.
    ull Ar[8], Ai[8];
    {
        float prr = 1.f, pri = 0.f;
#pragma unroll
        for (int w = 0; w < 4; w++) {
            int b = (l >> (3 - w)) & 1;
            float qr = b ? S[w] * S[w] : C[w] * C[w];
            float qi = -S[w] * C[w];
            float nr = prr * qr - pri * qi;
            pri = prr * qi + pri * qr;
            prr = nr;
        }
        float sr[8], si[8];
        sr[0] = prr; si[0] = pri;
        int cnt = 1;
#pragma unroll
        for (int w = 6; w >= 4; w--) {      // wire w -> j bit (6-w)
            float q0r = C[w] * C[w], q1r = S[w] * S[w], qi = -S[w] * C[w];
#pragma unroll
            for (int j = 0; j < 4; j++) {
                if (j < cnt) {
                    float br = sr[j], bi = si[j];
                    sr[j + cnt] = br * q1r - bi * qi;
                    si[j + cnt] = br * qi + bi * q1r;
                    sr[j] = br * q0r - bi * qi;
                    si[j] = br * qi + bi * q0r;
                }
            }
            cnt <<= 1;
        }
        // wire 7 on packed half: half0 *= (C7^2,-S7C7), half1 *= (S7^2,-S7C7)
        ull qrP = pk(C[7] * C[7], S[7] * S[7]);
        ull qiP = dup2(-S[7] * C[7]);
        ull nqiP = qiP ^ SGN2;
#pragma unroll
        for (int j = 0; j < 8; j++) {
            ull srj = dup2(sr[j]), sij = dup2(si[j]);
            Ar[j] = fma2(nqiP, sij, mul2(qrP, srj));
            Ai[j] = fma2(qiP,  srj, mul2(qrP, sij));
        }
    }

#define G(L, I, MM, RR) { float4 u = __ldg(&g_ucoef[(L) * 8 + (I)]); \
                          apply_gate8<MM, RR>(Ar, Ai, u, l); }
    // layer 1 (identity frame)
    G(0,0,0x80,0x80) G(0,1,0x40,0x40) G(0,2,0x20,0x20) G(0,3,0x10,0x10)
    G(0,4,0x08,0x08) G(0,5,0x04,0x04) G(0,6,0x02,0x02) G(0,7,0x01,0x01)
    // layer 2
    G(1,0,0xC0,0x80) G(1,1,0x60,0xC0) G(1,2,0x30,0xE0) G(1,3,0x18,0xF0)
    G(1,4,0x0C,0xF8) G(1,5,0x06,0xFC) G(1,6,0x03,0xFE) G(1,7,0x01,0xFF)
    // layer 3
    G(2,0,0xA0,0x80) G(2,1,0x50,0x40) G(2,2,0x28,0xA0) G(2,3,0x14,0x50)
    G(2,4,0x0A,0xA8) G(2,5,0x05,0x54) G(2,6,0x02,0xAA) G(2,7,0x01,0x55)
    // layer 4
    G(3,0,0xF0,0x80) G(3,1,0x78,0xC0) G(3,2,0x3C,0x60) G(3,3,0x1E,0x30)
    G(3,4,0x0F,0x98) G(3,5,0x07,0xCC) G(3,6,0x03,0x66) G(3,7,0x01,0x33)
#undef G

    // probabilities and signed local sums
    ull P[8];
#pragma unroll
    for (int j = 0; j < 8; j++) P[j] = fma2(Ai[j], Ai[j], mul2(Ar[j], Ar[j]));

    ull s1[4], d1[4];
#pragma unroll
    for (int k = 0; k < 4; k++) { s1[k] = add2(P[2 * k], P[2 * k + 1]);
                                  d1[k] = sub2(P[2 * k], P[2 * k + 1]); }
    ull s2a = add2(s1[0], s1[1]), s2b = add2(s1[2], s1[3]);
    ull d2a = sub2(s1[0], s1[1]), d2b = sub2(s1[2], s1[3]);
    ull T2  = add2(s2a, s2b);                 // all +
    ull D4  = sub2(s2a, s2b);                 // sign: j bit2 (wire4)
    ull D2  = add2(d2a, d2b);                 // sign: j bit1 (wire5)
    ull D1  = add2(add2(d1[0], d1[1]), add2(d1[2], d1[3]));  // j bit0 (wire6)

    float tx, ty; up2(T2, tx, ty);
    float ptot = tx + ty;                     // total prob (this lane)
    float Ah   = tx - ty;                     // sign: packed half (wire7)
    float ax, ay; up2(D4, ax, ay); float Aj4 = ax + ay;
    float bx, by; up2(D2, bx, by); float Aj2 = bx + by;
    float cx, cy; up2(D1, cx, cy); float Aj1 = cx + cy;

    // ev sign rows Rf = [0x80,0x40,0x20,0x10,0x88,0x44,0x22,0x11]
    float e0 = (l & 8) ? -ptot : ptot;
    float e1 = (l & 4) ? -ptot : ptot;
    float e2 = (l & 2) ? -ptot : ptot;
    float e3 = (l & 1) ? -ptot : ptot;
    float e4 = (l & 8) ? -Aj4 : Aj4;
    float e5 = (l & 4) ? -Aj2 : Aj2;
    float e6 = (l & 2) ? -Aj1 : Aj1;
    float e7 = (l & 1) ? -Ah  : Ah;

    ull E[4] = { pk(e0, e1), pk(e2, e3), pk(e4, e5), pk(e6, e7) };
#pragma unroll
    for (int off = 8; off; off >>= 1)
#pragma unroll
        for (int k = 0; k < 4; k++)
            E[k] = add2(E[k], shflx(E[k], off));

    float myev = 0.f;
#pragma unroll
    for (int o = 0; o < 8; o++) {
        if (l == o) {
            float vx, vy; up2(E[o >> 1], vx, vy);
            myev = (o & 1) ? vy : vx;
        }
    }
    if (l < 8)
        ev_s[rib * NQ + l] = myev;
    __syncthreads();

    // ---------------- Phase B: out = ev @ Wout^T + bout -------------------
    const float4* wo4 = reinterpret_cast<const float4*>(Wout);  // [DOUT][2]
    ull w[4][8];
    ull bo[4];
#pragma unroll
    for (int pp = 0; pp < 4; pp++) {
        int c0p = ((pp < 2) ? tid * 4 : 512 + tid * 4) + (pp & 1) * 2;
        float4 wa0 = __ldg(&wo4[c0p * 2 + 0]);
        float4 wa1 = __ldg(&wo4[c0p * 2 + 1]);
        float4 wb0 = __ldg(&wo4[(c0p + 1) * 2 + 0]);
        float4 wb1 = __ldg(&wo4[(c0p + 1) * 2 + 1]);
        w[pp][0] = pk(wa0.x, wb0.x); w[pp][1] = pk(wa0.y, wb0.y);
        w[pp][2] = pk(wa0.z, wb0.z); w[pp][3] = pk(wa0.w, wb0.w);
        w[pp][4] = pk(wa1.x, wb1.x); w[pp][5] = pk(wa1.y, wb1.y);
        w[pp][6] = pk(wa1.z, wb1.z); w[pp][7] = pk(wa1.w, wb1.w);
        bo[pp] = pk(__ldg(&bout[c0p]), __ldg(&bout[c0p + 1]));
    }

    float4* out4 = reinterpret_cast<float4*>(out);
#pragma unroll
    for (int r = 0; r < 8; r++) {
        ull acc0 = bo[0], acc1 = bo[1], acc2 = bo[2], acc3 = bo[3];
#pragma unroll
        for (int q = 0; q < NQ; q++) {
            ull eq = dup2(ev_s[r * NQ + q]);
            acc0 = fma2(w[0][q], eq, acc0);
            acc1 = fma2(w[1][q], eq, acc1);
            acc2 = fma2(w[2][q], eq, acc2);
            acc3 = fma2(w[3][q], eq, acc3);
        }
        float4 oA, oB;
        up2(acc0, oA.x, oA.y); up2(acc1, oA.z, oA.w);
        up2(acc2, oB.x, oB.y); up2(acc3, oB.z, oB.w);
        size_t base = (size_t)(row0 + r) * (DOUT / 4);
        out4[base + tid]       = oA;
        out4[base + 128 + tid] = oB;
    }
}

extern "C" void kernel_launch(void* const* d_in, const int* in_sizes, int n_in,
                              void* d_out, int out_size) {
    const float* x    = (const float*)d_in[0];
    const float* Win  = (const float*)d_in[1];
    const float* bin  = (const float*)d_in[2];
    const float* qw   = (const float*)d_in[3];
    const float* Wout = (const float*)d_in[4];
    const float* bout = (const float*)d_in[5];
    float* out = (float*)d_out;

    int B = in_sizes[0] / DIN;            // 8192
    k1_angles<<<B / 8, 128>>>(x, Win, bin, qw);
    k23_circuit_out<<<B / 8, 128>>>(Wout, bout, out);
}